// round 4
// baseline (speedup 1.0000x reference)
#include <cuda_runtime.h>
#include <math.h>

#define D_MODEL   1024
#define N_HEADS   16
#define HEAD_DIM  64
#define D_FF      4096
#define SEQ       2048
#define BATCH     2
#define M_ROWS    (BATCH * SEQ)   // 4096
#define EPS       1e-5f

// ---------------------------------------------------------------------------
// Scratch (device globals -- no allocations allowed)
// ---------------------------------------------------------------------------
__device__ float g_nx [M_ROWS * D_MODEL];   // LN1 output
__device__ float g_q  [M_ROWS * D_MODEL];   // [B,H,S,d]
__device__ float g_k  [M_ROWS * D_MODEL];   // [B,H,S,d]
__device__ float g_v  [M_ROWS * D_MODEL];   // [B,H,S,d]
__device__ float g_ctx[M_ROWS * D_MODEL];   // attention out, [B,S,D]
__device__ float g_x2 [M_ROWS * D_MODEL];   // x + attn proj
__device__ float g_nx2[M_ROWS * D_MODEL];   // LN2 output
__device__ float g_ffh[M_ROWS * D_FF];      // relu(ff1)

// ---------------------------------------------------------------------------
// LayerNorm: one block per row of 1024, 256 threads (1 float4 each)
// ---------------------------------------------------------------------------
__global__ __launch_bounds__(256) void ln_kernel(
    const float* __restrict__ x, const float* __restrict__ g,
    const float* __restrict__ b, float* __restrict__ out)
{
    int row = blockIdx.x;
    int t   = threadIdx.x;
    const float4* xr = reinterpret_cast<const float4*>(x + (size_t)row * D_MODEL);
    float4 v = xr[t];
    float s  = v.x + v.y + v.z + v.w;
    float ss = v.x * v.x + v.y * v.y + v.z * v.z + v.w * v.w;
    #pragma unroll
    for (int o = 16; o > 0; o >>= 1) {
        s  += __shfl_xor_sync(0xffffffffu, s,  o);
        ss += __shfl_xor_sync(0xffffffffu, ss, o);
    }
    __shared__ float shs[8], shss[8];
    int w = t >> 5;
    if ((t & 31) == 0) { shs[w] = s; shss[w] = ss; }
    __syncthreads();
    float tot = 0.f, tot2 = 0.f;
    #pragma unroll
    for (int i = 0; i < 8; i++) { tot += shs[i]; tot2 += shss[i]; }
    float mu  = tot * (1.0f / D_MODEL);
    float var = tot2 * (1.0f / D_MODEL) - mu * mu;
    float inv = rsqrtf(var + EPS);
    float4 gv = reinterpret_cast<const float4*>(g)[t];
    float4 bv = reinterpret_cast<const float4*>(b)[t];
    float4 o;
    o.x = (v.x - mu) * inv * gv.x + bv.x;
    o.y = (v.y - mu) * inv * gv.y + bv.y;
    o.z = (v.z - mu) * inv * gv.z + bv.z;
    o.w = (v.w - mu) * inv * gv.w + bv.w;
    reinterpret_cast<float4*>(out + (size_t)row * D_MODEL)[t] = o;
}

// ---------------------------------------------------------------------------
// SGEMM 128x128x16, 256 threads, 8x8 per thread.
// A: MxK row-major, B: KxN row-major. Epilogue modes:
//   1: out = acc + bias, scattered to [B,H,S,d] head layout
//   2: out = relu(acc + bias)
//   3: out = acc + bias + res   (res same layout as out)
// ---------------------------------------------------------------------------
#define BM 128
#define BN 128
#define BK 16
#define SA 132   // padded stride for transposed A tile (div by 4, not 32)

template<int MODE>
__global__ __launch_bounds__(256) void sgemm_kernel(
    const float* __restrict__ A, const float* __restrict__ B,
    const float* __restrict__ bias, const float* __restrict__ res,
    float* __restrict__ C, int Mdim, int Ndim, int Kdim)
{
    __shared__ float As[BK][SA];
    __shared__ float Bs[BK][BN];
    int tid  = threadIdx.x;
    int row0 = blockIdx.y * BM;
    int col0 = blockIdx.x * BN;
    int tm   = (tid >> 4) * 8;   // 0..120
    int tn   = (tid & 15) * 8;   // 0..120
    float acc[8][8] = {};

    int ar  = tid >> 2;          // A tile row (0..63), +64 on second pass
    int ac4 = (tid & 3) * 4;     // A tile col (0,4,8,12)
    int br  = tid >> 5;          // B tile row (0..7), +8 on second pass
    int bc4 = (tid & 31) * 4;    // B tile col

    for (int kb = 0; kb < Kdim; kb += BK) {
        #pragma unroll
        for (int p = 0; p < 2; p++) {
            int r = ar + p * 64;
            float4 va = *reinterpret_cast<const float4*>(
                A + (size_t)(row0 + r) * Kdim + kb + ac4);
            As[ac4 + 0][r] = va.x;
            As[ac4 + 1][r] = va.y;
            As[ac4 + 2][r] = va.z;
            As[ac4 + 3][r] = va.w;
        }
        #pragma unroll
        for (int p = 0; p < 2; p++) {
            int r = br + p * 8;
            *reinterpret_cast<float4*>(&Bs[r][bc4]) =
                *reinterpret_cast<const float4*>(
                    B + (size_t)(kb + r) * Ndim + col0 + bc4);
        }
        __syncthreads();
        #pragma unroll
        for (int k = 0; k < BK; k++) {
            float aA[8], aB[8];
            *reinterpret_cast<float4*>(aA)     = *reinterpret_cast<float4*>(&As[k][tm]);
            *reinterpret_cast<float4*>(aA + 4) = *reinterpret_cast<float4*>(&As[k][tm + 4]);
            *reinterpret_cast<float4*>(aB)     = *reinterpret_cast<float4*>(&Bs[k][tn]);
            *reinterpret_cast<float4*>(aB + 4) = *reinterpret_cast<float4*>(&Bs[k][tn + 4]);
            #pragma unroll
            for (int i = 0; i < 8; i++)
                #pragma unroll
                for (int j = 0; j < 8; j++)
                    acc[i][j] = fmaf(aA[i], aB[j], acc[i][j]);
        }
        __syncthreads();
    }

    #pragma unroll
    for (int i = 0; i < 8; i++) {
        int m = row0 + tm + i;
        #pragma unroll
        for (int j = 0; j < 8; j += 4) {
            int n = col0 + tn + j;
            float4 bb = *reinterpret_cast<const float4*>(bias + n);
            float4 o;
            o.x = acc[i][j + 0] + bb.x;
            o.y = acc[i][j + 1] + bb.y;
            o.z = acc[i][j + 2] + bb.z;
            o.w = acc[i][j + 3] + bb.w;
            if (MODE == 2) {
                o.x = fmaxf(o.x, 0.f); o.y = fmaxf(o.y, 0.f);
                o.z = fmaxf(o.z, 0.f); o.w = fmaxf(o.w, 0.f);
            }
            if (MODE == 3) {
                float4 rr = *reinterpret_cast<const float4*>(res + (size_t)m * Ndim + n);
                o.x += rr.x; o.y += rr.y; o.z += rr.z; o.w += rr.w;
            }
            if (MODE == 1) {
                int bb_ = m >> 11;        // m / SEQ
                int s_  = m & (SEQ - 1);
                int h_  = n >> 6;         // n / HEAD_DIM
                int dd  = n & (HEAD_DIM - 1);
                float* dst = C + ((size_t)((bb_ * N_HEADS + h_) * SEQ + s_)) * HEAD_DIM + dd;
                *reinterpret_cast<float4*>(dst) = o;
            } else {
                *reinterpret_cast<float4*>(C + (size_t)m * Ndim + n) = o;
            }
        }
    }
}

// ---------------------------------------------------------------------------
// Fused flash attention, fp32. 128-query tile / block, 128 threads (16x8),
// 8x8 register tiles in both the QK^T and PV phases, online softmax with
// 8-lane shuffle row reductions. Q/K/V in [B,H,S,d]; output scattered to
// [B,S,D].
// ---------------------------------------------------------------------------
#define ATTN_BQ  128
#define ATTN_BK  64
#define ATTN_ST  65   // odd stride -> conflict-free scalar row access
#define ATTN_SMEM ((ATTN_BQ*ATTN_ST + 2*ATTN_BK*ATTN_ST + ATTN_BQ*ATTN_ST) * 4)

__global__ __launch_bounds__(128) void attn_kernel(
    const float* __restrict__ Q, const float* __restrict__ K,
    const float* __restrict__ V, float* __restrict__ ctx)
{
    extern __shared__ float sm[];
    float* Qs = sm;                            // [128][65]
    float* Ks = Qs + ATTN_BQ * ATTN_ST;        // [64][65]
    float* Vs = Ks + ATTN_BK * ATTN_ST;        // [64][65]
    float* Ps = Vs + ATTN_BK * ATTN_ST;        // [128][65]

    int bh  = blockIdx.y;               // b*16 + h
    int q0  = blockIdx.x * ATTN_BQ;
    int tid = threadIdx.x;
    int ty  = tid >> 3;                 // 0..15 -> q rows ty*8..+7
    int tx  = tid & 7;                  // 0..7  -> k cols / dims tx*8..+7

    const float* Qg = Q + ((size_t)bh * SEQ + q0) * HEAD_DIM;
    const float* Kg = K + (size_t)bh * SEQ * HEAD_DIM;
    const float* Vg = V + (size_t)bh * SEQ * HEAD_DIM;

    // Load Q tile (pre-scaled by 1/sqrt(64))
    for (int f = tid; f < ATTN_BQ * 16; f += 128) {
        int r = f >> 4, c = (f & 15) * 4;
        float4 v = *reinterpret_cast<const float4*>(Qg + (size_t)r * HEAD_DIM + c);
        Qs[r * ATTN_ST + c + 0] = v.x * 0.125f;
        Qs[r * ATTN_ST + c + 1] = v.y * 0.125f;
        Qs[r * ATTN_ST + c + 2] = v.z * 0.125f;
        Qs[r * ATTN_ST + c + 3] = v.w * 0.125f;
    }

    float acc[8][8] = {};
    float mrow[8], lrow[8];
    #pragma unroll
    for (int i = 0; i < 8; i++) { mrow[i] = -1e30f; lrow[i] = 0.f; }

    for (int kt = 0; kt < SEQ; kt += ATTN_BK) {
        __syncthreads();   // prev iteration done reading Ks/Vs/Ps
        for (int f = tid; f < ATTN_BK * 16; f += 128) {
            int r = f >> 4, c = (f & 15) * 4;
            float4 kv = *reinterpret_cast<const float4*>(Kg + (size_t)(kt + r) * HEAD_DIM + c);
            Ks[r * ATTN_ST + c + 0] = kv.x;
            Ks[r * ATTN_ST + c + 1] = kv.y;
            Ks[r * ATTN_ST + c + 2] = kv.z;
            Ks[r * ATTN_ST + c + 3] = kv.w;
            float4 vv = *reinterpret_cast<const float4*>(Vg + (size_t)(kt + r) * HEAD_DIM + c);
            Vs[r * ATTN_ST + c + 0] = vv.x;
            Vs[r * ATTN_ST + c + 1] = vv.y;
            Vs[r * ATTN_ST + c + 2] = vv.z;
            Vs[r * ATTN_ST + c + 3] = vv.w;
        }
        __syncthreads();

        // S = Q * K^T (scaled)
        float s[8][8] = {};
        #pragma unroll 4
        for (int d = 0; d < HEAD_DIM; d++) {
            float aQ[8], aK[8];
            #pragma unroll
            for (int i = 0; i < 8; i++) aQ[i] = Qs[(ty * 8 + i) * ATTN_ST + d];
            #pragma unroll
            for (int j = 0; j < 8; j++) aK[j] = Ks[(tx * 8 + j) * ATTN_ST + d];
            #pragma unroll
            for (int i = 0; i < 8; i++)
                #pragma unroll
                for (int j = 0; j < 8; j++)
                    s[i][j] = fmaf(aQ[i], aK[j], s[i][j]);
        }

        // Online softmax update per q-row (8 lanes share a row)
        #pragma unroll
        for (int i = 0; i < 8; i++) {
            float mx = s[i][0];
            #pragma unroll
            for (int j = 1; j < 8; j++) mx = fmaxf(mx, s[i][j]);
            mx = fmaxf(mx, __shfl_xor_sync(0xffffffffu, mx, 1));
            mx = fmaxf(mx, __shfl_xor_sync(0xffffffffu, mx, 2));
            mx = fmaxf(mx, __shfl_xor_sync(0xffffffffu, mx, 4));
            float mnew = fmaxf(mrow[i], mx);
            float corr = __expf(mrow[i] - mnew);
            mrow[i] = mnew;
            float rs = 0.f;
            #pragma unroll
            for (int j = 0; j < 8; j++) {
                s[i][j] = __expf(s[i][j] - mnew);
                rs += s[i][j];
            }
            rs += __shfl_xor_sync(0xffffffffu, rs, 1);
            rs += __shfl_xor_sync(0xffffffffu, rs, 2);
            rs += __shfl_xor_sync(0xffffffffu, rs, 4);
            lrow[i] = lrow[i] * corr + rs;
            #pragma unroll
            for (int j = 0; j < 8; j++) acc[i][j] *= corr;
            #pragma unroll
            for (int j = 0; j < 8; j++)
                Ps[(ty * 8 + i) * ATTN_ST + tx * 8 + j] = s[i][j];
        }
        __syncthreads();

        // O += P * V
        #pragma unroll 4
        for (int k = 0; k < ATTN_BK; k++) {
            float aP[8], aV[8];
            #pragma unroll
            for (int i = 0; i < 8; i++) aP[i] = Ps[(ty * 8 + i) * ATTN_ST + k];
            #pragma unroll
            for (int j = 0; j < 8; j++) aV[j] = Vs[k * ATTN_ST + tx * 8 + j];
            #pragma unroll
            for (int i = 0; i < 8; i++)
                #pragma unroll
                for (int j = 0; j < 8; j++)
                    acc[i][j] = fmaf(aP[i], aV[j], acc[i][j]);
        }
    }

    // Write ctx[b, s, h*64 + d]
    int b_ = bh >> 4, h_ = bh & 15;
    #pragma unroll
    for (int i = 0; i < 8; i++) {
        int qrow  = q0 + ty * 8 + i;
        float inv = 1.0f / lrow[i];
        float* dst = ctx + ((size_t)(b_ * SEQ + qrow)) * D_MODEL + h_ * HEAD_DIM + tx * 8;
        float4 o1, o2;
        o1.x = acc[i][0] * inv; o1.y = acc[i][1] * inv;
        o1.z = acc[i][2] * inv; o1.w = acc[i][3] * inv;
        o2.x = acc[i][4] * inv; o2.y = acc[i][5] * inv;
        o2.z = acc[i][6] * inv; o2.w = acc[i][7] * inv;
        *reinterpret_cast<float4*>(dst)     = o1;
        *reinterpret_cast<float4*>(dst + 4) = o2;
    }
}

// ---------------------------------------------------------------------------
// Launch
// ---------------------------------------------------------------------------
extern "C" void kernel_launch(void* const* d_in, const int* in_sizes, int n_in,
                              void* d_out, int out_size)
{
    const float* x   = (const float*)d_in[0];
    const float* wq  = (const float*)d_in[1];
    const float* bq  = (const float*)d_in[2];
    const float* wk  = (const float*)d_in[3];
    const float* bk  = (const float*)d_in[4];
    const float* wv  = (const float*)d_in[5];
    const float* bv  = (const float*)d_in[6];
    const float* wo  = (const float*)d_in[7];
    const float* bo  = (const float*)d_in[8];
    const float* w1  = (const float*)d_in[9];
    const float* b1  = (const float*)d_in[10];
    const float* w2  = (const float*)d_in[11];
    const float* b2  = (const float*)d_in[12];
    const float* g1  = (const float*)d_in[13];
    const float* be1 = (const float*)d_in[14];
    const float* g2  = (const float*)d_in[15];
    const float* be2 = (const float*)d_in[16];
    float* out = (float*)d_out;

    float *nx, *q, *k, *v, *ctx, *x2, *nx2, *ffh;
    cudaGetSymbolAddress((void**)&nx,  g_nx);
    cudaGetSymbolAddress((void**)&q,   g_q);
    cudaGetSymbolAddress((void**)&k,   g_k);
    cudaGetSymbolAddress((void**)&v,   g_v);
    cudaGetSymbolAddress((void**)&ctx, g_ctx);
    cudaGetSymbolAddress((void**)&x2,  g_x2);
    cudaGetSymbolAddress((void**)&nx2, g_nx2);
    cudaGetSymbolAddress((void**)&ffh, g_ffh);

    cudaFuncSetAttribute(attn_kernel,
                         cudaFuncAttributeMaxDynamicSharedMemorySize, ATTN_SMEM);

    dim3 gD (D_MODEL / BN, M_ROWS / BM);   // (8, 32)
    dim3 gFF(D_FF   / BN, M_ROWS / BM);    // (32, 32)

    // LN1
    ln_kernel<<<M_ROWS, 256>>>(x, g1, be1, nx);
    // QKV projections (scatter to head layout)
    sgemm_kernel<1><<<gD, 256>>>(nx, wq, bq, nullptr, q, M_ROWS, D_MODEL, D_MODEL);
    sgemm_kernel<1><<<gD, 256>>>(nx, wk, bk, nullptr, k, M_ROWS, D_MODEL, D_MODEL);
    sgemm_kernel<1><<<gD, 256>>>(nx, wv, bv, nullptr, v, M_ROWS, D_MODEL, D_MODEL);
    // Attention
    attn_kernel<<<dim3(SEQ / ATTN_BQ, BATCH * N_HEADS), 128, ATTN_SMEM>>>(q, k, v, ctx);
    // O projection + residual
    sgemm_kernel<3><<<gD, 256>>>(ctx, wo, bo, x, x2, M_ROWS, D_MODEL, D_MODEL);
    // LN2
    ln_kernel<<<M_ROWS, 256>>>(x2, g2, be2, nx2);
    // FF1 (relu)
    sgemm_kernel<2><<<gFF, 256>>>(nx2, w1, b1, nullptr, ffh, M_ROWS, D_FF, D_MODEL);
    // FF2 + residual -> output
    sgemm_kernel<3><<<gD, 256>>>(ffh, w2, b2, x2, out, M_ROWS, D_MODEL, D_FF);
}

// round 5
// speedup vs baseline: 1.7752x; 1.7752x over previous
#include <cuda_runtime.h>
#include <math.h>

#define D_MODEL   1024
#define N_HEADS   16
#define HEAD_DIM  64
#define D_FF      4096
#define SEQ       2048
#define BATCH     2
#define M_ROWS    (BATCH * SEQ)   // 4096
#define EPS       1e-5f

// ---------------------------------------------------------------------------
// Scratch (device globals -- no allocations allowed)
// ---------------------------------------------------------------------------
__device__ float g_nx [M_ROWS * D_MODEL];   // LN1 output
__device__ float g_q  [M_ROWS * D_MODEL];   // [B,H,S,d]
__device__ float g_k  [M_ROWS * D_MODEL];   // [B,H,S,d]
__device__ float g_v  [M_ROWS * D_MODEL];   // [B,H,S,d]
__device__ float g_ctx[M_ROWS * D_MODEL];   // attention out, [B,S,D]
__device__ float g_x2 [M_ROWS * D_MODEL];   // x + attn proj
__device__ float g_nx2[M_ROWS * D_MODEL];   // LN2 output
__device__ float g_ffh[M_ROWS * D_FF];      // relu(ff1)

// ---------------------------------------------------------------------------
// LayerNorm: one block per row of 1024, 256 threads (1 float4 each)
// ---------------------------------------------------------------------------
__global__ __launch_bounds__(256) void ln_kernel(
    const float* __restrict__ x, const float* __restrict__ g,
    const float* __restrict__ b, float* __restrict__ out)
{
    int row = blockIdx.x;
    int t   = threadIdx.x;
    const float4* xr = reinterpret_cast<const float4*>(x + (size_t)row * D_MODEL);
    float4 v = xr[t];
    float s  = v.x + v.y + v.z + v.w;
    float ss = v.x * v.x + v.y * v.y + v.z * v.z + v.w * v.w;
    #pragma unroll
    for (int o = 16; o > 0; o >>= 1) {
        s  += __shfl_xor_sync(0xffffffffu, s,  o);
        ss += __shfl_xor_sync(0xffffffffu, ss, o);
    }
    __shared__ float shs[8], shss[8];
    int w = t >> 5;
    if ((t & 31) == 0) { shs[w] = s; shss[w] = ss; }
    __syncthreads();
    float tot = 0.f, tot2 = 0.f;
    #pragma unroll
    for (int i = 0; i < 8; i++) { tot += shs[i]; tot2 += shss[i]; }
    float mu  = tot * (1.0f / D_MODEL);
    float var = tot2 * (1.0f / D_MODEL) - mu * mu;
    float inv = rsqrtf(var + EPS);
    float4 gv = reinterpret_cast<const float4*>(g)[t];
    float4 bv = reinterpret_cast<const float4*>(b)[t];
    float4 o;
    o.x = (v.x - mu) * inv * gv.x + bv.x;
    o.y = (v.y - mu) * inv * gv.y + bv.y;
    o.z = (v.z - mu) * inv * gv.z + bv.z;
    o.w = (v.w - mu) * inv * gv.w + bv.w;
    reinterpret_cast<float4*>(out + (size_t)row * D_MODEL)[t] = o;
}

// ---------------------------------------------------------------------------
// TF32 tensor-core GEMM: 128x128x32 block tile, 256 threads (8 warps),
// warp tile 64x32 (4x4 mma.m16n8k8 tiles). A: MxK row-major, B: KxN
// row-major, fp32 in/out, tf32 (RNA-rounded) inside.
// Epilogue modes:
//   1: out = acc + bias, scattered to [B,H,S,d] head layout
//   2: out = relu(acc + bias)
//   3: out = acc + bias + res   (res same layout as out)
// ---------------------------------------------------------------------------
#define BM 128
#define BN 128
#define BK 32
#define AS_ST 36    // As stride: bank = 4*g + tig -> conflict-free frags
#define BS_ST 136   // Bs stride: bank = 8*tig + g -> conflict-free frags

__device__ __forceinline__ unsigned f2tf32(float x) {
    unsigned y;
    asm("cvt.rna.tf32.f32 %0, %1;" : "=r"(y) : "f"(x));
    return y;
}

__device__ __forceinline__ void mma_tf32(float* c, const unsigned* a, const unsigned* b) {
    asm volatile(
        "mma.sync.aligned.m16n8k8.row.col.f32.tf32.tf32.f32 "
        "{%0,%1,%2,%3}, {%4,%5,%6,%7}, {%8,%9}, {%0,%1,%2,%3};"
        : "+f"(c[0]), "+f"(c[1]), "+f"(c[2]), "+f"(c[3])
        : "r"(a[0]), "r"(a[1]), "r"(a[2]), "r"(a[3]),
          "r"(b[0]), "r"(b[1]));
}

template<int MODE>
__global__ __launch_bounds__(256) void mmagemm_kernel(
    const float* __restrict__ A, const float* __restrict__ B,
    const float* __restrict__ bias, const float* __restrict__ res,
    float* __restrict__ C, int Mdim, int Ndim, int Kdim)
{
    __shared__ unsigned As[BM][AS_ST];   // [m][k], tf32 bits
    __shared__ unsigned Bs[BK][BS_ST];   // [k][n], tf32 bits

    int tid  = threadIdx.x;
    int lane = tid & 31;
    int warp = tid >> 5;
    int wm   = warp >> 2;    // 0..1
    int wn   = warp & 3;     // 0..3
    int g    = lane >> 2;    // groupID 0..7
    int tg   = lane & 3;     // threadID_in_group 0..3
    int row0 = blockIdx.y * BM;
    int col0 = blockIdx.x * BN;

    float acc[4][4][4];
    #pragma unroll
    for (int i = 0; i < 4; i++)
        #pragma unroll
        for (int j = 0; j < 4; j++)
            #pragma unroll
            for (int q = 0; q < 4; q++) acc[i][j][q] = 0.f;

    for (int kb = 0; kb < Kdim; kb += BK) {
        // ---- load A tile: 128 rows x 32 k, float4 per thread x4 ----
        #pragma unroll
        for (int p = 0; p < 4; p++) {
            int f  = tid + p * 256;
            int r  = f >> 3;
            int k4 = (f & 7) * 4;
            float4 va = *reinterpret_cast<const float4*>(
                A + (size_t)(row0 + r) * Kdim + kb + k4);
            uint4 ua;
            ua.x = f2tf32(va.x); ua.y = f2tf32(va.y);
            ua.z = f2tf32(va.z); ua.w = f2tf32(va.w);
            *reinterpret_cast<uint4*>(&As[r][k4]) = ua;
        }
        // ---- load B tile: 32 k x 128 n ----
        #pragma unroll
        for (int p = 0; p < 4; p++) {
            int f  = tid + p * 256;
            int kk = f >> 5;
            int n4 = (f & 31) * 4;
            float4 vb = *reinterpret_cast<const float4*>(
                B + (size_t)(kb + kk) * Ndim + col0 + n4);
            uint4 ub;
            ub.x = f2tf32(vb.x); ub.y = f2tf32(vb.y);
            ub.z = f2tf32(vb.z); ub.w = f2tf32(vb.w);
            *reinterpret_cast<uint4*>(&Bs[kk][n4]) = ub;
        }
        __syncthreads();

        #pragma unroll
        for (int s = 0; s < 4; s++) {       // k8 steps within BK
            int k0 = s * 8;
            unsigned af[4][4];
            #pragma unroll
            for (int mt = 0; mt < 4; mt++) {
                int r = wm * 64 + mt * 16 + g;
                af[mt][0] = As[r    ][k0 + tg];
                af[mt][1] = As[r + 8][k0 + tg];
                af[mt][2] = As[r    ][k0 + tg + 4];
                af[mt][3] = As[r + 8][k0 + tg + 4];
            }
            unsigned bf[4][2];
            #pragma unroll
            for (int nt = 0; nt < 4; nt++) {
                int n = wn * 32 + nt * 8 + g;
                bf[nt][0] = Bs[k0 + tg    ][n];
                bf[nt][1] = Bs[k0 + tg + 4][n];
            }
            #pragma unroll
            for (int mt = 0; mt < 4; mt++)
                #pragma unroll
                for (int nt = 0; nt < 4; nt++)
                    mma_tf32(acc[mt][nt], af[mt], bf[nt]);
        }
        __syncthreads();
    }

    // ---- epilogue: c0=(r0, n), c1=(r0, n+1), c2=(r0+8, n), c3=(r0+8, n+1)
    #pragma unroll
    for (int mt = 0; mt < 4; mt++) {
        int m1 = row0 + wm * 64 + mt * 16 + g;
        int m2 = m1 + 8;
        #pragma unroll
        for (int nt = 0; nt < 4; nt++) {
            int n = col0 + wn * 32 + nt * 8 + 2 * tg;
            float2 bb = *reinterpret_cast<const float2*>(bias + n);
            float2 o1, o2;
            o1.x = acc[mt][nt][0] + bb.x;
            o1.y = acc[mt][nt][1] + bb.y;
            o2.x = acc[mt][nt][2] + bb.x;
            o2.y = acc[mt][nt][3] + bb.y;
            if (MODE == 2) {
                o1.x = fmaxf(o1.x, 0.f); o1.y = fmaxf(o1.y, 0.f);
                o2.x = fmaxf(o2.x, 0.f); o2.y = fmaxf(o2.y, 0.f);
            }
            if (MODE == 3) {
                float2 r1 = *reinterpret_cast<const float2*>(res + (size_t)m1 * Ndim + n);
                float2 r2 = *reinterpret_cast<const float2*>(res + (size_t)m2 * Ndim + n);
                o1.x += r1.x; o1.y += r1.y;
                o2.x += r2.x; o2.y += r2.y;
            }
            if (MODE == 1) {
                int h_ = n >> 6;
                int dd = n & (HEAD_DIM - 1);
                int b1_ = m1 >> 11, s1_ = m1 & (SEQ - 1);
                int b2_ = m2 >> 11, s2_ = m2 & (SEQ - 1);
                float* d1 = C + ((size_t)((b1_ * N_HEADS + h_) * SEQ + s1_)) * HEAD_DIM + dd;
                float* d2 = C + ((size_t)((b2_ * N_HEADS + h_) * SEQ + s2_)) * HEAD_DIM + dd;
                *reinterpret_cast<float2*>(d1) = o1;
                *reinterpret_cast<float2*>(d2) = o2;
            } else {
                *reinterpret_cast<float2*>(C + (size_t)m1 * Ndim + n) = o1;
                *reinterpret_cast<float2*>(C + (size_t)m2 * Ndim + n) = o2;
            }
        }
    }
}

// ---------------------------------------------------------------------------
// Fused flash attention, fp32. 128-query tile / block, 128 threads (16x8),
// 8x8 register tiles in both the QK^T and PV phases, online softmax with
// 8-lane shuffle row reductions. Q/K/V in [B,H,S,d]; output scattered to
// [B,S,D].
// ---------------------------------------------------------------------------
#define ATTN_BQ  128
#define ATTN_BK  64
#define ATTN_ST  65
#define ATTN_SMEM ((ATTN_BQ*ATTN_ST + 2*ATTN_BK*ATTN_ST + ATTN_BQ*ATTN_ST) * 4)

__global__ __launch_bounds__(128) void attn_kernel(
    const float* __restrict__ Q, const float* __restrict__ K,
    const float* __restrict__ V, float* __restrict__ ctx)
{
    extern __shared__ float sm[];
    float* Qs = sm;                            // [128][65]
    float* Ks = Qs + ATTN_BQ * ATTN_ST;        // [64][65]
    float* Vs = Ks + ATTN_BK * ATTN_ST;        // [64][65]
    float* Ps = Vs + ATTN_BK * ATTN_ST;        // [128][65]

    int bh  = blockIdx.y;
    int q0  = blockIdx.x * ATTN_BQ;
    int tid = threadIdx.x;
    int ty  = tid >> 3;
    int tx  = tid & 7;

    const float* Qg = Q + ((size_t)bh * SEQ + q0) * HEAD_DIM;
    const float* Kg = K + (size_t)bh * SEQ * HEAD_DIM;
    const float* Vg = V + (size_t)bh * SEQ * HEAD_DIM;

    for (int f = tid; f < ATTN_BQ * 16; f += 128) {
        int r = f >> 4, c = (f & 15) * 4;
        float4 v = *reinterpret_cast<const float4*>(Qg + (size_t)r * HEAD_DIM + c);
        Qs[r * ATTN_ST + c + 0] = v.x * 0.125f;
        Qs[r * ATTN_ST + c + 1] = v.y * 0.125f;
        Qs[r * ATTN_ST + c + 2] = v.z * 0.125f;
        Qs[r * ATTN_ST + c + 3] = v.w * 0.125f;
    }

    float acc[8][8] = {};
    float mrow[8], lrow[8];
    #pragma unroll
    for (int i = 0; i < 8; i++) { mrow[i] = -1e30f; lrow[i] = 0.f; }

    for (int kt = 0; kt < SEQ; kt += ATTN_BK) {
        __syncthreads();
        for (int f = tid; f < ATTN_BK * 16; f += 128) {
            int r = f >> 4, c = (f & 15) * 4;
            float4 kv = *reinterpret_cast<const float4*>(Kg + (size_t)(kt + r) * HEAD_DIM + c);
            Ks[r * ATTN_ST + c + 0] = kv.x;
            Ks[r * ATTN_ST + c + 1] = kv.y;
            Ks[r * ATTN_ST + c + 2] = kv.z;
            Ks[r * ATTN_ST + c + 3] = kv.w;
            float4 vv = *reinterpret_cast<const float4*>(Vg + (size_t)(kt + r) * HEAD_DIM + c);
            Vs[r * ATTN_ST + c + 0] = vv.x;
            Vs[r * ATTN_ST + c + 1] = vv.y;
            Vs[r * ATTN_ST + c + 2] = vv.z;
            Vs[r * ATTN_ST + c + 3] = vv.w;
        }
        __syncthreads();

        float s[8][8] = {};
        #pragma unroll 4
        for (int d = 0; d < HEAD_DIM; d++) {
            float aQ[8], aK[8];
            #pragma unroll
            for (int i = 0; i < 8; i++) aQ[i] = Qs[(ty * 8 + i) * ATTN_ST + d];
            #pragma unroll
            for (int j = 0; j < 8; j++) aK[j] = Ks[(tx * 8 + j) * ATTN_ST + d];
            #pragma unroll
            for (int i = 0; i < 8; i++)
                #pragma unroll
                for (int j = 0; j < 8; j++)
                    s[i][j] = fmaf(aQ[i], aK[j], s[i][j]);
        }

        #pragma unroll
        for (int i = 0; i < 8; i++) {
            float mx = s[i][0];
            #pragma unroll
            for (int j = 1; j < 8; j++) mx = fmaxf(mx, s[i][j]);
            mx = fmaxf(mx, __shfl_xor_sync(0xffffffffu, mx, 1));
            mx = fmaxf(mx, __shfl_xor_sync(0xffffffffu, mx, 2));
            mx = fmaxf(mx, __shfl_xor_sync(0xffffffffu, mx, 4));
            float mnew = fmaxf(mrow[i], mx);
            float corr = __expf(mrow[i] - mnew);
            mrow[i] = mnew;
            float rs = 0.f;
            #pragma unroll
            for (int j = 0; j < 8; j++) {
                s[i][j] = __expf(s[i][j] - mnew);
                rs += s[i][j];
            }
            rs += __shfl_xor_sync(0xffffffffu, rs, 1);
            rs += __shfl_xor_sync(0xffffffffu, rs, 2);
            rs += __shfl_xor_sync(0xffffffffu, rs, 4);
            lrow[i] = lrow[i] * corr + rs;
            #pragma unroll
            for (int j = 0; j < 8; j++) acc[i][j] *= corr;
            #pragma unroll
            for (int j = 0; j < 8; j++)
                Ps[(ty * 8 + i) * ATTN_ST + tx * 8 + j] = s[i][j];
        }
        __syncthreads();

        #pragma unroll 4
        for (int k = 0; k < ATTN_BK; k++) {
            float aP[8], aV[8];
            #pragma unroll
            for (int i = 0; i < 8; i++) aP[i] = Ps[(ty * 8 + i) * ATTN_ST + k];
            #pragma unroll
            for (int j = 0; j < 8; j++) aV[j] = Vs[k * ATTN_ST + tx * 8 + j];
            #pragma unroll
            for (int i = 0; i < 8; i++)
                #pragma unroll
                for (int j = 0; j < 8; j++)
                    acc[i][j] = fmaf(aP[i], aV[j], acc[i][j]);
        }
    }

    int b_ = bh >> 4, h_ = bh & 15;
    #pragma unroll
    for (int i = 0; i < 8; i++) {
        int qrow  = q0 + ty * 8 + i;
        float inv = 1.0f / lrow[i];
        float* dst = ctx + ((size_t)(b_ * SEQ + qrow)) * D_MODEL + h_ * HEAD_DIM + tx * 8;
        float4 o1, o2;
        o1.x = acc[i][0] * inv; o1.y = acc[i][1] * inv;
        o1.z = acc[i][2] * inv; o1.w = acc[i][3] * inv;
        o2.x = acc[i][4] * inv; o2.y = acc[i][5] * inv;
        o2.z = acc[i][6] * inv; o2.w = acc[i][7] * inv;
        *reinterpret_cast<float4*>(dst)     = o1;
        *reinterpret_cast<float4*>(dst + 4) = o2;
    }
}

// ---------------------------------------------------------------------------
// Launch
// ---------------------------------------------------------------------------
extern "C" void kernel_launch(void* const* d_in, const int* in_sizes, int n_in,
                              void* d_out, int out_size)
{
    const float* x   = (const float*)d_in[0];
    const float* wq  = (const float*)d_in[1];
    const float* bq  = (const float*)d_in[2];
    const float* wk  = (const float*)d_in[3];
    const float* bk  = (const float*)d_in[4];
    const float* wv  = (const float*)d_in[5];
    const float* bv  = (const float*)d_in[6];
    const float* wo  = (const float*)d_in[7];
    const float* bo  = (const float*)d_in[8];
    const float* w1  = (const float*)d_in[9];
    const float* b1  = (const float*)d_in[10];
    const float* w2  = (const float*)d_in[11];
    const float* b2  = (const float*)d_in[12];
    const float* g1  = (const float*)d_in[13];
    const float* be1 = (const float*)d_in[14];
    const float* g2  = (const float*)d_in[15];
    const float* be2 = (const float*)d_in[16];
    float* out = (float*)d_out;

    float *nx, *q, *k, *v, *ctx, *x2, *nx2, *ffh;
    cudaGetSymbolAddress((void**)&nx,  g_nx);
    cudaGetSymbolAddress((void**)&q,   g_q);
    cudaGetSymbolAddress((void**)&k,   g_k);
    cudaGetSymbolAddress((void**)&v,   g_v);
    cudaGetSymbolAddress((void**)&ctx, g_ctx);
    cudaGetSymbolAddress((void**)&x2,  g_x2);
    cudaGetSymbolAddress((void**)&nx2, g_nx2);
    cudaGetSymbolAddress((void**)&ffh, g_ffh);

    cudaFuncSetAttribute(attn_kernel,
                         cudaFuncAttributeMaxDynamicSharedMemorySize, ATTN_SMEM);

    dim3 gD (D_MODEL / BN, M_ROWS / BM);   // (8, 32)
    dim3 gFF(D_FF   / BN, M_ROWS / BM);    // (32, 32)

    // LN1
    ln_kernel<<<M_ROWS, 256>>>(x, g1, be1, nx);
    // QKV projections (scatter to head layout), tf32 tensor cores
    mmagemm_kernel<1><<<gD, 256>>>(nx, wq, bq, nullptr, q, M_ROWS, D_MODEL, D_MODEL);
    mmagemm_kernel<1><<<gD, 256>>>(nx, wk, bk, nullptr, k, M_ROWS, D_MODEL, D_MODEL);
    mmagemm_kernel<1><<<gD, 256>>>(nx, wv, bv, nullptr, v, M_ROWS, D_MODEL, D_MODEL);
    // Attention (fp32)
    attn_kernel<<<dim3(SEQ / ATTN_BQ, BATCH * N_HEADS), 128, ATTN_SMEM>>>(q, k, v, ctx);
    // O projection + residual
    mmagemm_kernel<3><<<gD, 256>>>(ctx, wo, bo, x, x2, M_ROWS, D_MODEL, D_MODEL);
    // LN2
    ln_kernel<<<M_ROWS, 256>>>(x2, g2, be2, nx2);
    // FF1 (relu)
    mmagemm_kernel<2><<<gFF, 256>>>(nx2, w1, b1, nullptr, ffh, M_ROWS, D_FF, D_MODEL);
    // FF2 + residual -> output
    mmagemm_kernel<3><<<gD, 256>>>(ffh, w2, b2, x2, out, M_ROWS, D_MODEL, D_FF);
}

// round 8
// speedup vs baseline: 3.0844x; 1.7375x over previous
#include <cuda_runtime.h>
#include <math.h>

#define D_MODEL   1024
#define N_HEADS   16
#define HEAD_DIM  64
#define D_FF      4096
#define SEQ       2048
#define BATCH     2
#define M_ROWS    (BATCH * SEQ)   // 4096
#define EPS       1e-5f

// ---------------------------------------------------------------------------
// Scratch (device globals -- no allocations allowed)
// ---------------------------------------------------------------------------
__device__ float g_nx [M_ROWS * D_MODEL];
__device__ float g_q  [M_ROWS * D_MODEL];   // [B,H,S,d]
__device__ float g_k  [M_ROWS * D_MODEL];
__device__ float g_v  [M_ROWS * D_MODEL];
__device__ float g_ctx[M_ROWS * D_MODEL];   // [B,S,D]
__device__ float g_x2 [M_ROWS * D_MODEL];
__device__ float g_nx2[M_ROWS * D_MODEL];
__device__ float g_ffh[M_ROWS * D_FF];

__device__ __forceinline__ unsigned f2tf32(float x) {
    unsigned y;
    asm("cvt.rna.tf32.f32 %0, %1;" : "=r"(y) : "f"(x));
    return y;
}

__device__ __forceinline__ void mma_tf32(float* c, const unsigned* a, const unsigned* b) {
    asm volatile(
        "mma.sync.aligned.m16n8k8.row.col.f32.tf32.tf32.f32 "
        "{%0,%1,%2,%3}, {%4,%5,%6,%7}, {%8,%9}, {%0,%1,%2,%3};"
        : "+f"(c[0]), "+f"(c[1]), "+f"(c[2]), "+f"(c[3])
        : "r"(a[0]), "r"(a[1]), "r"(a[2]), "r"(a[3]),
          "r"(b[0]), "r"(b[1]));
}

#define CP_ASYNC16(dst, src) \
    asm volatile("cp.async.cg.shared.global [%0], [%1], 16;" :: "r"(dst), "l"(src))

// ---------------------------------------------------------------------------
// LayerNorm
// ---------------------------------------------------------------------------
__global__ __launch_bounds__(256) void ln_kernel(
    const float* __restrict__ x, const float* __restrict__ g,
    const float* __restrict__ b, float* __restrict__ out)
{
    int row = blockIdx.x;
    int t   = threadIdx.x;
    const float4* xr = reinterpret_cast<const float4*>(x + (size_t)row * D_MODEL);
    float4 v = xr[t];
    float s  = v.x + v.y + v.z + v.w;
    float ss = v.x * v.x + v.y * v.y + v.z * v.z + v.w * v.w;
    #pragma unroll
    for (int o = 16; o > 0; o >>= 1) {
        s  += __shfl_xor_sync(0xffffffffu, s,  o);
        ss += __shfl_xor_sync(0xffffffffu, ss, o);
    }
    __shared__ float shs[8], shss[8];
    int w = t >> 5;
    if ((t & 31) == 0) { shs[w] = s; shss[w] = ss; }
    __syncthreads();
    float tot = 0.f, tot2 = 0.f;
    #pragma unroll
    for (int i = 0; i < 8; i++) { tot += shs[i]; tot2 += shss[i]; }
    float mu  = tot * (1.0f / D_MODEL);
    float var = tot2 * (1.0f / D_MODEL) - mu * mu;
    float inv = rsqrtf(var + EPS);
    float4 gv = reinterpret_cast<const float4*>(g)[t];
    float4 bv = reinterpret_cast<const float4*>(b)[t];
    float4 o;
    o.x = (v.x - mu) * inv * gv.x + bv.x;
    o.y = (v.y - mu) * inv * gv.y + bv.y;
    o.z = (v.z - mu) * inv * gv.z + bv.z;
    o.w = (v.w - mu) * inv * gv.w + bv.w;
    reinterpret_cast<float4*>(out + (size_t)row * D_MODEL)[t] = o;
}

// ---------------------------------------------------------------------------
// TF32 GEMM: 128x128x32 tile, 8 warps (warp tile 64x32), cp.async
// double-buffered smem (fp32 in smem, cvt at fragment load).
// MODE 1: bias + head-scatter; 2: relu(bias); 3: bias + residual.
// ---------------------------------------------------------------------------
#define BM 128
#define BN 128
#define BK 32
#define AS_ST 36    // %32==4 -> A-frag bank = 4g+tg, conflict-free
#define BS_ST 136   // %32==8 -> B-frag bank = 8tg+g, conflict-free
#define GEMM_SMEM ((2*BM*AS_ST + 2*BK*BS_ST) * 4)

template<int MODE>
__global__ __launch_bounds__(256) void mmagemm_kernel(
    const float* __restrict__ A, const float* __restrict__ B,
    const float* __restrict__ bias, const float* __restrict__ res,
    float* __restrict__ C, int Ndim, int Kdim)
{
    extern __shared__ float smf[];
    float* As = smf;                       // [2][BM][AS_ST]
    float* Bs = smf + 2 * BM * AS_ST;      // [2][BK][BS_ST]

    int tid  = threadIdx.x;
    int lane = tid & 31;
    int warp = tid >> 5;
    int wm   = warp >> 2;
    int wn   = warp & 3;
    int g    = lane >> 2;
    int tg   = lane & 3;
    int row0 = blockIdx.y * BM;
    int col0 = blockIdx.x * BN;

    float acc[4][4][4] = {};

    auto issue_stage = [&](int kb, int buf) {
        float* Ab = As + buf * BM * AS_ST;
        float* Bb = Bs + buf * BK * BS_ST;
        #pragma unroll
        for (int p = 0; p < 4; p++) {
            int f = tid + p * 256, r = f >> 3, k4 = (f & 7) * 4;
            unsigned d = (unsigned)__cvta_generic_to_shared(Ab + r * AS_ST + k4);
            CP_ASYNC16(d, A + (size_t)(row0 + r) * Kdim + kb + k4);
        }
        #pragma unroll
        for (int p = 0; p < 4; p++) {
            int f = tid + p * 256, kk = f >> 5, n4 = (f & 31) * 4;
            unsigned d = (unsigned)__cvta_generic_to_shared(Bb + kk * BS_ST + n4);
            CP_ASYNC16(d, B + (size_t)(kb + kk) * Ndim + col0 + n4);
        }
        asm volatile("cp.async.commit_group;");
    };

    issue_stage(0, 0);
    int nk = Kdim / BK;
    for (int t = 0; t < nk; t++) {
        int buf = t & 1;
        if (t + 1 < nk) {
            issue_stage((t + 1) * BK, buf ^ 1);
            asm volatile("cp.async.wait_group 1;");
        } else {
            asm volatile("cp.async.wait_group 0;");
        }
        __syncthreads();
        const float* Ab = As + buf * BM * AS_ST;
        const float* Bb = Bs + buf * BK * BS_ST;
        #pragma unroll
        for (int s = 0; s < 4; s++) {
            int k0 = s * 8;
            unsigned af[4][4];
            #pragma unroll
            for (int mt = 0; mt < 4; mt++) {
                int r = wm * 64 + mt * 16 + g;
                af[mt][0] = f2tf32(Ab[r * AS_ST + k0 + tg]);
                af[mt][1] = f2tf32(Ab[(r + 8) * AS_ST + k0 + tg]);
                af[mt][2] = f2tf32(Ab[r * AS_ST + k0 + tg + 4]);
                af[mt][3] = f2tf32(Ab[(r + 8) * AS_ST + k0 + tg + 4]);
            }
            unsigned bf[4][2];
            #pragma unroll
            for (int nt = 0; nt < 4; nt++) {
                int n = wn * 32 + nt * 8 + g;
                bf[nt][0] = f2tf32(Bb[(k0 + tg) * BS_ST + n]);
                bf[nt][1] = f2tf32(Bb[(k0 + tg + 4) * BS_ST + n]);
            }
            #pragma unroll
            for (int mt = 0; mt < 4; mt++)
                #pragma unroll
                for (int nt = 0; nt < 4; nt++)
                    mma_tf32(acc[mt][nt], af[mt], bf[nt]);
        }
        __syncthreads();
    }

    #pragma unroll
    for (int mt = 0; mt < 4; mt++) {
        int m1 = row0 + wm * 64 + mt * 16 + g;
        int m2 = m1 + 8;
        #pragma unroll
        for (int nt = 0; nt < 4; nt++) {
            int n = col0 + wn * 32 + nt * 8 + 2 * tg;
            float2 bb = *reinterpret_cast<const float2*>(bias + n);
            float2 o1, o2;
            o1.x = acc[mt][nt][0] + bb.x;
            o1.y = acc[mt][nt][1] + bb.y;
            o2.x = acc[mt][nt][2] + bb.x;
            o2.y = acc[mt][nt][3] + bb.y;
            if (MODE == 2) {
                o1.x = fmaxf(o1.x, 0.f); o1.y = fmaxf(o1.y, 0.f);
                o2.x = fmaxf(o2.x, 0.f); o2.y = fmaxf(o2.y, 0.f);
            }
            if (MODE == 3) {
                float2 r1 = *reinterpret_cast<const float2*>(res + (size_t)m1 * Ndim + n);
                float2 r2 = *reinterpret_cast<const float2*>(res + (size_t)m2 * Ndim + n);
                o1.x += r1.x; o1.y += r1.y;
                o2.x += r2.x; o2.y += r2.y;
            }
            if (MODE == 1) {
                int h_ = n >> 6;
                int dd = n & (HEAD_DIM - 1);
                int b1_ = m1 >> 11, s1_ = m1 & (SEQ - 1);
                int b2_ = m2 >> 11, s2_ = m2 & (SEQ - 1);
                float* d1 = C + ((size_t)((b1_ * N_HEADS + h_) * SEQ + s1_)) * HEAD_DIM + dd;
                float* d2 = C + ((size_t)((b2_ * N_HEADS + h_) * SEQ + s2_)) * HEAD_DIM + dd;
                *reinterpret_cast<float2*>(d1) = o1;
                *reinterpret_cast<float2*>(d2) = o2;
            } else {
                *reinterpret_cast<float2*>(C + (size_t)m1 * Ndim + n) = o1;
                *reinterpret_cast<float2*>(C + (size_t)m2 * Ndim + n) = o2;
            }
        }
    }
}

// ---------------------------------------------------------------------------
// Flash attention on tensor cores (tf32 mma). 128 q-rows/block, 8 warps.
// Each warp owns 16 FULL q-rows across the whole 64-wide kv tile, so the
// softmax row state (m, l) is entirely warp-local (reduce over tg lanes
// only). P staged via warp-private smem rows (tf32 bits) into A-fragments.
// ---------------------------------------------------------------------------
#define QS_ST 68   // %32==4
#define KS_ST 68
#define VS_ST 72   // %32==8
#define PS_ST 68
#define ATTN_SMEM ((128*QS_ST + 64*KS_ST + 64*VS_ST + 128*PS_ST) * 4)

__global__ __launch_bounds__(256) void attn_kernel(
    const float* __restrict__ Q, const float* __restrict__ K,
    const float* __restrict__ V, float* __restrict__ ctx)
{
    extern __shared__ unsigned smu[];
    unsigned* Qs = smu;                    // [128][68]  (m x d)
    unsigned* Ks = Qs + 128 * QS_ST;       // [64][68]   (kv x d)
    unsigned* Vs = Ks + 64 * KS_ST;        // [64][72]   (kv x d)
    unsigned* Ps = Vs + 64 * VS_ST;        // [128][68]  (m x kv), warp-private rows

    int bh   = blockIdx.y;
    int q0   = blockIdx.x * 128;
    int tid  = threadIdx.x;
    int lane = tid & 31;
    int warp = tid >> 5;                   // warp owns rows warp*16 .. +15
    int g    = lane >> 2;
    int tg   = lane & 3;
    int r0   = warp * 16 + g;              // fragment row (and r0+8)

    const float* Qg = Q + ((size_t)bh * SEQ + q0) * HEAD_DIM;
    const float* Kg = K + (size_t)bh * SEQ * HEAD_DIM;
    const float* Vg = V + (size_t)bh * SEQ * HEAD_DIM;

    // Q tile (pre-scaled by 1/sqrt(64))
    #pragma unroll
    for (int p = 0; p < 8; p++) {
        int f = tid + p * 256, r = f >> 4, c = (f & 15) * 4;
        float4 v = *reinterpret_cast<const float4*>(Qg + (size_t)r * HEAD_DIM + c);
        Qs[r * QS_ST + c + 0] = f2tf32(v.x * 0.125f);
        Qs[r * QS_ST + c + 1] = f2tf32(v.y * 0.125f);
        Qs[r * QS_ST + c + 2] = f2tf32(v.z * 0.125f);
        Qs[r * QS_ST + c + 3] = f2tf32(v.w * 0.125f);
    }

    float m[2] = {-1e30f, -1e30f};
    float l[2] = {0.f, 0.f};
    float acc[8][4] = {};                  // O: 16 rows x 64 d (8 n-tiles)

    for (int kt = 0; kt < SEQ; kt += 64) {
        __syncthreads();   // prior iter done reading Ks/Vs
        #pragma unroll
        for (int p = 0; p < 4; p++) {
            int f = tid + p * 256, r = f >> 4, c = (f & 15) * 4;
            float4 kv = *reinterpret_cast<const float4*>(Kg + (size_t)(kt + r) * HEAD_DIM + c);
            Ks[r * KS_ST + c + 0] = f2tf32(kv.x);
            Ks[r * KS_ST + c + 1] = f2tf32(kv.y);
            Ks[r * KS_ST + c + 2] = f2tf32(kv.z);
            Ks[r * KS_ST + c + 3] = f2tf32(kv.w);
            float4 vv = *reinterpret_cast<const float4*>(Vg + (size_t)(kt + r) * HEAD_DIM + c);
            Vs[r * VS_ST + c + 0] = f2tf32(vv.x);
            Vs[r * VS_ST + c + 1] = f2tf32(vv.y);
            Vs[r * VS_ST + c + 2] = f2tf32(vv.z);
            Vs[r * VS_ST + c + 3] = f2tf32(vv.w);
        }
        __syncthreads();

        // ---- S = Q K^T : 16 rows x 64 kv (1 m-tile x 8 n-tiles x 8 k-steps)
        float s[8][4] = {};
        #pragma unroll
        for (int k8 = 0; k8 < 8; k8++) {
            int k0 = k8 * 8;
            unsigned aq[4];
            aq[0] = Qs[r0 * QS_ST + k0 + tg];
            aq[1] = Qs[(r0 + 8) * QS_ST + k0 + tg];
            aq[2] = Qs[r0 * QS_ST + k0 + tg + 4];
            aq[3] = Qs[(r0 + 8) * QS_ST + k0 + tg + 4];
            #pragma unroll
            for (int nt = 0; nt < 8; nt++) {
                int n = nt * 8 + g;
                unsigned bk[2];
                bk[0] = Ks[n * KS_ST + k0 + tg];
                bk[1] = Ks[n * KS_ST + k0 + tg + 4];
                mma_tf32(s[nt], aq, bk);
            }
        }

        // ---- online softmax: rows r0 (h2=0), r0+8 (h2=1); full 64-col row
        //      is covered by this warp's 8 nt tiles + 4 tg lanes.
        #pragma unroll
        for (int h2 = 0; h2 < 2; h2++) {
            float mx = -1e30f;
            #pragma unroll
            for (int nt = 0; nt < 8; nt++)
                mx = fmaxf(mx, fmaxf(s[nt][h2 * 2], s[nt][h2 * 2 + 1]));
            mx = fmaxf(mx, __shfl_xor_sync(0xffffffffu, mx, 1));
            mx = fmaxf(mx, __shfl_xor_sync(0xffffffffu, mx, 2));
            float mnew = fmaxf(m[h2], mx);
            float corr = __expf(m[h2] - mnew);
            m[h2] = mnew;
            int row = warp * 16 + h2 * 8 + g;
            float rs = 0.f;
            #pragma unroll
            for (int nt = 0; nt < 8; nt++) {
                float e0 = __expf(s[nt][h2 * 2]     - mnew);
                float e1 = __expf(s[nt][h2 * 2 + 1] - mnew);
                rs += e0 + e1;
                int cc = nt * 8 + 2 * tg;
                Ps[row * PS_ST + cc]     = f2tf32(e0);
                Ps[row * PS_ST + cc + 1] = f2tf32(e1);
            }
            rs += __shfl_xor_sync(0xffffffffu, rs, 1);
            rs += __shfl_xor_sync(0xffffffffu, rs, 2);
            l[h2] = l[h2] * corr + rs;
            #pragma unroll
            for (int nt = 0; nt < 8; nt++) {
                acc[nt][h2 * 2]     *= corr;
                acc[nt][h2 * 2 + 1] *= corr;
            }
        }
        __syncwarp();      // Ps rows are warp-private

        // ---- O += P V : 16 rows x 64 d (8 k-steps x 8 n-tiles)
        #pragma unroll
        for (int k8 = 0; k8 < 8; k8++) {
            int k0 = k8 * 8;
            unsigned ap[4];
            ap[0] = Ps[r0 * PS_ST + k0 + tg];
            ap[1] = Ps[(r0 + 8) * PS_ST + k0 + tg];
            ap[2] = Ps[r0 * PS_ST + k0 + tg + 4];
            ap[3] = Ps[(r0 + 8) * PS_ST + k0 + tg + 4];
            #pragma unroll
            for (int nt = 0; nt < 8; nt++) {
                int n = nt * 8 + g;
                unsigned bv[2];
                bv[0] = Vs[(k0 + tg) * VS_ST + n];
                bv[1] = Vs[(k0 + tg + 4) * VS_ST + n];
                mma_tf32(acc[nt], ap, bv);
            }
        }
    }

    // ---- write ctx[b, s, h*64 + d]
    int b_ = bh >> 4, h_ = bh & 15;
    #pragma unroll
    for (int h2 = 0; h2 < 2; h2++) {
        int row   = q0 + warp * 16 + h2 * 8 + g;
        float inv = 1.0f / l[h2];
        float* dst = ctx + ((size_t)(b_ * SEQ + row)) * D_MODEL + h_ * HEAD_DIM;
        #pragma unroll
        for (int nt = 0; nt < 8; nt++) {
            int cc = nt * 8 + 2 * tg;
            float2 o;
            o.x = acc[nt][h2 * 2]     * inv;
            o.y = acc[nt][h2 * 2 + 1] * inv;
            *reinterpret_cast<float2*>(dst + cc) = o;
        }
    }
}

// ---------------------------------------------------------------------------
// Launch
// ---------------------------------------------------------------------------
extern "C" void kernel_launch(void* const* d_in, const int* in_sizes, int n_in,
                              void* d_out, int out_size)
{
    const float* x   = (const float*)d_in[0];
    const float* wq  = (const float*)d_in[1];
    const float* bq  = (const float*)d_in[2];
    const float* wk  = (const float*)d_in[3];
    const float* bk  = (const float*)d_in[4];
    const float* wv  = (const float*)d_in[5];
    const float* bv  = (const float*)d_in[6];
    const float* wo  = (const float*)d_in[7];
    const float* bo  = (const float*)d_in[8];
    const float* w1  = (const float*)d_in[9];
    const float* b1  = (const float*)d_in[10];
    const float* w2  = (const float*)d_in[11];
    const float* b2  = (const float*)d_in[12];
    const float* g1  = (const float*)d_in[13];
    const float* be1 = (const float*)d_in[14];
    const float* g2  = (const float*)d_in[15];
    const float* be2 = (const float*)d_in[16];
    float* out = (float*)d_out;

    float *nx, *q, *k, *v, *ctx, *x2, *nx2, *ffh;
    cudaGetSymbolAddress((void**)&nx,  g_nx);
    cudaGetSymbolAddress((void**)&q,   g_q);
    cudaGetSymbolAddress((void**)&k,   g_k);
    cudaGetSymbolAddress((void**)&v,   g_v);
    cudaGetSymbolAddress((void**)&ctx, g_ctx);
    cudaGetSymbolAddress((void**)&x2,  g_x2);
    cudaGetSymbolAddress((void**)&nx2, g_nx2);
    cudaGetSymbolAddress((void**)&ffh, g_ffh);

    cudaFuncSetAttribute(mmagemm_kernel<1>,
                         cudaFuncAttributeMaxDynamicSharedMemorySize, GEMM_SMEM);
    cudaFuncSetAttribute(mmagemm_kernel<2>,
                         cudaFuncAttributeMaxDynamicSharedMemorySize, GEMM_SMEM);
    cudaFuncSetAttribute(mmagemm_kernel<3>,
                         cudaFuncAttributeMaxDynamicSharedMemorySize, GEMM_SMEM);
    cudaFuncSetAttribute(attn_kernel,
                         cudaFuncAttributeMaxDynamicSharedMemorySize, ATTN_SMEM);

    dim3 gD (D_MODEL / BN, M_ROWS / BM);   // (8, 32)
    dim3 gFF(D_FF   / BN, M_ROWS / BM);    // (32, 32)

    ln_kernel<<<M_ROWS, 256>>>(x, g1, be1, nx);
    mmagemm_kernel<1><<<gD, 256, GEMM_SMEM>>>(nx, wq, bq, nullptr, q, D_MODEL, D_MODEL);
    mmagemm_kernel<1><<<gD, 256, GEMM_SMEM>>>(nx, wk, bk, nullptr, k, D_MODEL, D_MODEL);
    mmagemm_kernel<1><<<gD, 256, GEMM_SMEM>>>(nx, wv, bv, nullptr, v, D_MODEL, D_MODEL);
    attn_kernel<<<dim3(SEQ / 128, BATCH * N_HEADS), 256, ATTN_SMEM>>>(q, k, v, ctx);
    mmagemm_kernel<3><<<gD, 256, GEMM_SMEM>>>(ctx, wo, bo, x, x2, D_MODEL, D_MODEL);
    ln_kernel<<<M_ROWS, 256>>>(x2, g2, be2, nx2);
    mmagemm_kernel<2><<<gFF, 256, GEMM_SMEM>>>(nx2, w1, b1, nullptr, ffh, D_FF, D_MODEL);
    mmagemm_kernel<3><<<gD, 256, GEMM_SMEM>>>(ffh, w2, b2, x2, out, D_MODEL, D_FF);
}